// round 1
// baseline (speedup 1.0000x reference)
#include <cuda_runtime.h>

#define NN 100000
#define EE 1600000
#define HD 128

// ---- device scratch (allocation-free contract: __device__ globals) ----
__device__ float g_deg[NN];
__device__ float g_dinv[NN];
__device__ float g_G[NN * HD];    // dinv-scaled features (messages)
__device__ float g_ACC[NN * HD];  // aggregation accumulator (init = G, self-loop)
__device__ float g_X2[NN * HD];   // layer output / next layer input

// ------------------------------------------------------------------
// degree kernels
// ------------------------------------------------------------------
__global__ void zero_deg_kernel(int n) {
    int i = blockIdx.x * blockDim.x + threadIdx.x;
    if (i < n) g_deg[i] = 0.0f;
}

__global__ void count_deg_kernel(const int* __restrict__ dst, int e) {
    int i = blockIdx.x * blockDim.x + threadIdx.x;
    if (i < e) atomicAdd(&g_deg[dst[i]], 1.0f);
}

__global__ void calc_dinv_kernel(int n) {
    int i = blockIdx.x * blockDim.x + threadIdx.x;
    if (i < n) g_dinv[i] = rsqrtf(g_deg[i] + 1.0f);  // +1 self loop
}

// ------------------------------------------------------------------
// GEMM: H = X @ W  (K=128, N=128), epilogue: G = H * dinv, ACC = G
// 64 rows/block, 256 threads, full K in shared.
// Shared: Ws[128][132], Xt[128][68] (X transposed: [k][row])
// ------------------------------------------------------------------
#define GEMM_SMEM ((128 * 132 + 128 * 68) * 4)

__global__ __launch_bounds__(256) void gemm128_kernel(
    const float* __restrict__ Xext, const float* __restrict__ W,
    int n, int use_x2)
{
    extern __shared__ float sm[];
    float* Ws = sm;               // stride 132 floats
    float* Xt = sm + 128 * 132;   // stride 68 floats, [k][row]

    const float* X = use_x2 ? g_X2 : Xext;

    int tid = threadIdx.x;
    int row0 = blockIdx.x * 64;

    // load W [128][128] row-major -> Ws (stride 132)
    for (int idx = tid; idx < 128 * 32; idx += 256) {
        int r = idx >> 5, c4 = idx & 31;
        float4 v = *(const float4*)(W + r * 128 + c4 * 4);
        *(float4*)(Ws + r * 132 + c4 * 4) = v;
    }
    // load X tile [64][128] -> transposed Xt[k][row]
    for (int idx = tid; idx < 64 * 32; idx += 256) {
        int r = idx >> 5, k4 = idx & 31;
        int grow = row0 + r;
        float4 v = (grow < n) ? *(const float4*)(X + (size_t)grow * 128 + k4 * 4)
                              : make_float4(0.f, 0.f, 0.f, 0.f);
        Xt[(k4 * 4 + 0) * 68 + r] = v.x;
        Xt[(k4 * 4 + 1) * 68 + r] = v.y;
        Xt[(k4 * 4 + 2) * 68 + r] = v.z;
        Xt[(k4 * 4 + 3) * 68 + r] = v.w;
    }
    __syncthreads();

    int tx = tid & 15;   // column quad: cols tx*4..+3 and 64+tx*4..+3
    int ty = tid >> 4;   // row quad: rows ty*4..+3

    float acc[4][8];
#pragma unroll
    for (int i = 0; i < 4; i++)
#pragma unroll
        for (int j = 0; j < 8; j++) acc[i][j] = 0.0f;

#pragma unroll 8
    for (int k = 0; k < 128; k++) {
        float4 a  = *(const float4*)(Xt + k * 68 + ty * 4);
        float4 b0 = *(const float4*)(Ws + k * 132 + tx * 4);
        float4 b1 = *(const float4*)(Ws + k * 132 + 64 + tx * 4);
        float av[4] = {a.x, a.y, a.z, a.w};
        float bv[8] = {b0.x, b0.y, b0.z, b0.w, b1.x, b1.y, b1.z, b1.w};
#pragma unroll
        for (int i = 0; i < 4; i++)
#pragma unroll
            for (int j = 0; j < 8; j++)
                acc[i][j] = fmaf(av[i], bv[j], acc[i][j]);
    }

#pragma unroll
    for (int i = 0; i < 4; i++) {
        int row = row0 + ty * 4 + i;
        if (row >= n) continue;
        float dv = g_dinv[row];
        float4 o0 = make_float4(acc[i][0] * dv, acc[i][1] * dv,
                                acc[i][2] * dv, acc[i][3] * dv);
        float4 o1 = make_float4(acc[i][4] * dv, acc[i][5] * dv,
                                acc[i][6] * dv, acc[i][7] * dv);
        size_t base = (size_t)row * 128;
        *(float4*)(g_G + base + tx * 4) = o0;
        *(float4*)(g_G + base + 64 + tx * 4) = o1;
        *(float4*)(g_ACC + base + tx * 4) = o0;
        *(float4*)(g_ACC + base + 64 + tx * 4) = o1;
    }
}

// ------------------------------------------------------------------
// Edge aggregation: ACC[dst] += G[src]; one warp per edge.
// ------------------------------------------------------------------
__global__ __launch_bounds__(256) void edge_agg_kernel(
    const int* __restrict__ src, const int* __restrict__ dst, int e)
{
    int gid = blockIdx.x * blockDim.x + threadIdx.x;
    int edge = gid >> 5;
    int lane = gid & 31;
    if (edge >= e) return;
    int s = __ldg(&src[edge]);
    int d = __ldg(&dst[edge]);
    float4 v = *(const float4*)(g_G + (size_t)s * 128 + lane * 4);
    float* a = g_ACC + (size_t)d * 128 + lane * 4;
    atomicAdd(a + 0, v.x);
    atomicAdd(a + 1, v.y);
    atomicAdd(a + 2, v.z);
    atomicAdd(a + 3, v.w);
}

// ------------------------------------------------------------------
// Finalize: X2 = relu(dinv * ACC + b)   (writes next layer input)
// ------------------------------------------------------------------
__global__ __launch_bounds__(256) void finalize_kernel(
    const float* __restrict__ b, int n)
{
    int idx = blockIdx.x * blockDim.x + threadIdx.x;  // over n*32 float4s
    if (idx >= n * 32) return;
    int row = idx >> 5;
    int c4 = idx & 31;
    float dv = g_dinv[row];
    size_t off = (size_t)row * 128 + c4 * 4;
    float4 a = *(const float4*)(g_ACC + off);
    float4 o;
    o.x = fmaxf(fmaf(dv, a.x, __ldg(&b[c4 * 4 + 0])), 0.0f);
    o.y = fmaxf(fmaf(dv, a.y, __ldg(&b[c4 * 4 + 1])), 0.0f);
    o.z = fmaxf(fmaf(dv, a.z, __ldg(&b[c4 * 4 + 2])), 0.0f);
    o.w = fmaxf(fmaf(dv, a.w, __ldg(&b[c4 * 4 + 3])), 0.0f);
    *(float4*)(g_X2 + off) = o;
}

// ------------------------------------------------------------------
// Output GEMM: out = X2 @ Wout + bout   (K=128, N=40)
// 32 rows/block, 320 threads (40 cols x 8)
// ------------------------------------------------------------------
__global__ __launch_bounds__(320) void out_gemm_kernel(
    const float* __restrict__ Wout, const float* __restrict__ bout,
    float* __restrict__ out, int n)
{
    __shared__ float Ws[128 * 40];
    __shared__ float Xs[32][132];
    __shared__ float bs[40];

    int tid = threadIdx.x;
    int row0 = blockIdx.x * 32;

    for (int idx = tid; idx < 128 * 40; idx += 320) Ws[idx] = Wout[idx];
    if (tid < 40) bs[tid] = bout[tid];
    for (int idx = tid; idx < 32 * 32; idx += 320) {
        int r = idx >> 5, k4 = idx & 31;
        int gr = row0 + r;
        float4 v = (gr < n) ? *(const float4*)(g_X2 + (size_t)gr * 128 + k4 * 4)
                            : make_float4(0.f, 0.f, 0.f, 0.f);
        *(float4*)(&Xs[r][k4 * 4]) = v;
    }
    __syncthreads();

    int col = tid % 40;
    int ty = tid / 40;   // 0..7
    float acc[4] = {0.f, 0.f, 0.f, 0.f};
#pragma unroll 4
    for (int k = 0; k < 128; k++) {
        float w = Ws[k * 40 + col];
#pragma unroll
        for (int r = 0; r < 4; r++)
            acc[r] = fmaf(Xs[ty + 8 * r][k], w, acc[r]);
    }
#pragma unroll
    for (int r = 0; r < 4; r++) {
        int row = row0 + ty + 8 * r;
        if (row < n) out[(size_t)row * 40 + col] = acc[r] + bs[col];
    }
}

// ------------------------------------------------------------------
// launch
// ------------------------------------------------------------------
extern "C" void kernel_launch(void* const* d_in, const int* in_sizes, int n_in,
                              void* d_out, int out_size)
{
    const float* x    = (const float*)d_in[0];
    const int*   ei   = (const int*)d_in[1];
    const float* W1   = (const float*)d_in[2];
    const float* b1   = (const float*)d_in[3];
    const float* W2   = (const float*)d_in[4];
    const float* b2   = (const float*)d_in[5];
    const float* Wout = (const float*)d_in[6];
    const float* bout = (const float*)d_in[7];
    float* out = (float*)d_out;

    int n = in_sizes[0] / 128;
    int e = in_sizes[1] / 2;
    const int* src = ei;
    const int* dst = ei + e;

    cudaFuncSetAttribute(gemm128_kernel,
                         cudaFuncAttributeMaxDynamicSharedMemorySize, GEMM_SMEM);

    int nb_n = (n + 255) / 256;
    int nb_e = (e + 255) / 256;
    int nb_gemm = (n + 63) / 64;
    long long edge_threads = (long long)e * 32;
    int nb_edge = (int)((edge_threads + 255) / 256);
    int nb_fin = (n * 32 + 255) / 256;
    int nb_out = (n + 31) / 32;

    // degrees (shared across both layers)
    zero_deg_kernel<<<nb_n, 256>>>(n);
    count_deg_kernel<<<nb_e, 256>>>(dst, e);
    calc_dinv_kernel<<<nb_n, 256>>>(n);

    // layer 1
    gemm128_kernel<<<nb_gemm, 256, GEMM_SMEM>>>(x, W1, n, 0);
    edge_agg_kernel<<<nb_edge, 256>>>(src, dst, e);
    finalize_kernel<<<nb_fin, 256>>>(b1, n);

    // layer 2
    gemm128_kernel<<<nb_gemm, 256, GEMM_SMEM>>>(nullptr, W2, n, 1);
    edge_agg_kernel<<<nb_edge, 256>>>(src, dst, e);
    finalize_kernel<<<nb_fin, 256>>>(b2, n);

    // output projection
    out_gemm_kernel<<<nb_out, 320>>>(Wout, bout, out, n);
}

// round 2
// speedup vs baseline: 1.6510x; 1.6510x over previous
#include <cuda_runtime.h>

#define NN 100000
#define EE 1600000
#define HD 128

// ---- device scratch (allocation-free contract: __device__ globals) ----
__device__ float g_deg[NN];
__device__ float g_dinv[NN];
__device__ float g_G[NN * HD];    // dinv-scaled features (messages)
__device__ float g_ACC[NN * HD];  // aggregation accumulator (init = G, self-loop)
__device__ float g_X2[NN * HD];   // layer output / next layer input

// ------------------------------------------------------------------
// degree kernels
// ------------------------------------------------------------------
__global__ void zero_deg_kernel(int n) {
    int i = blockIdx.x * blockDim.x + threadIdx.x;
    if (i < n) g_deg[i] = 0.0f;
}

__global__ void count_deg_kernel(const int* __restrict__ dst, int e) {
    int i = blockIdx.x * blockDim.x + threadIdx.x;
    if (i < e) atomicAdd(&g_deg[dst[i]], 1.0f);
}

__global__ void calc_dinv_kernel(int n) {
    int i = blockIdx.x * blockDim.x + threadIdx.x;
    if (i < n) g_dinv[i] = rsqrtf(g_deg[i] + 1.0f);  // +1 self loop
}

// ------------------------------------------------------------------
// GEMM: H = X @ W  (K=128, N=128), epilogue: G = H * dinv, ACC = G
// 64 rows/block, 256 threads, full K in shared. ~77% of fp32 FFMA peak.
// ------------------------------------------------------------------
#define GEMM_SMEM ((128 * 132 + 128 * 68) * 4)

__global__ __launch_bounds__(256) void gemm128_kernel(
    const float* __restrict__ Xext, const float* __restrict__ W,
    int n, int use_x2)
{
    extern __shared__ float sm[];
    float* Ws = sm;               // stride 132 floats
    float* Xt = sm + 128 * 132;   // stride 68 floats, [k][row]

    const float* X = use_x2 ? g_X2 : Xext;

    int tid = threadIdx.x;
    int row0 = blockIdx.x * 64;

    // load W [128][128] row-major -> Ws (stride 132)
    for (int idx = tid; idx < 128 * 32; idx += 256) {
        int r = idx >> 5, c4 = idx & 31;
        float4 v = *(const float4*)(W + r * 128 + c4 * 4);
        *(float4*)(Ws + r * 132 + c4 * 4) = v;
    }
    // load X tile [64][128] -> transposed Xt[k][row]
    for (int idx = tid; idx < 64 * 32; idx += 256) {
        int r = idx >> 5, k4 = idx & 31;
        int grow = row0 + r;
        float4 v = (grow < n) ? *(const float4*)(X + (size_t)grow * 128 + k4 * 4)
                              : make_float4(0.f, 0.f, 0.f, 0.f);
        Xt[(k4 * 4 + 0) * 68 + r] = v.x;
        Xt[(k4 * 4 + 1) * 68 + r] = v.y;
        Xt[(k4 * 4 + 2) * 68 + r] = v.z;
        Xt[(k4 * 4 + 3) * 68 + r] = v.w;
    }
    __syncthreads();

    int tx = tid & 15;   // column quad: cols tx*4..+3 and 64+tx*4..+3
    int ty = tid >> 4;   // row quad: rows ty*4..+3

    float acc[4][8];
#pragma unroll
    for (int i = 0; i < 4; i++)
#pragma unroll
        for (int j = 0; j < 8; j++) acc[i][j] = 0.0f;

#pragma unroll 8
    for (int k = 0; k < 128; k++) {
        float4 a  = *(const float4*)(Xt + k * 68 + ty * 4);
        float4 b0 = *(const float4*)(Ws + k * 132 + tx * 4);
        float4 b1 = *(const float4*)(Ws + k * 132 + 64 + tx * 4);
        float av[4] = {a.x, a.y, a.z, a.w};
        float bv[8] = {b0.x, b0.y, b0.z, b0.w, b1.x, b1.y, b1.z, b1.w};
#pragma unroll
        for (int i = 0; i < 4; i++)
#pragma unroll
            for (int j = 0; j < 8; j++)
                acc[i][j] = fmaf(av[i], bv[j], acc[i][j]);
    }

#pragma unroll
    for (int i = 0; i < 4; i++) {
        int row = row0 + ty * 4 + i;
        if (row >= n) continue;
        float dv = g_dinv[row];
        float4 o0 = make_float4(acc[i][0] * dv, acc[i][1] * dv,
                                acc[i][2] * dv, acc[i][3] * dv);
        float4 o1 = make_float4(acc[i][4] * dv, acc[i][5] * dv,
                                acc[i][6] * dv, acc[i][7] * dv);
        size_t base = (size_t)row * 128;
        *(float4*)(g_G + base + tx * 4) = o0;
        *(float4*)(g_G + base + 64 + tx * 4) = o1;
        *(float4*)(g_ACC + base + tx * 4) = o0;
        *(float4*)(g_ACC + base + 64 + tx * 4) = o1;
    }
}

// ------------------------------------------------------------------
// Edge aggregation: ACC[dst] += G[src]; one warp per edge,
// one vectorized red.global.add.v4.f32 per thread (RED.E.128).
// ------------------------------------------------------------------
__device__ __forceinline__ void red_add_v4(float* addr, float4 v) {
    asm volatile("red.global.add.v4.f32 [%0], {%1, %2, %3, %4};"
                 :: "l"(addr), "f"(v.x), "f"(v.y), "f"(v.z), "f"(v.w)
                 : "memory");
}

__global__ __launch_bounds__(256) void edge_agg_kernel(
    const int* __restrict__ src, const int* __restrict__ dst, int e)
{
    int gid = blockIdx.x * blockDim.x + threadIdx.x;
    int edge = gid >> 5;
    int lane = gid & 31;
    if (edge >= e) return;
    int s = __ldg(&src[edge]);
    int d = __ldg(&dst[edge]);
    float4 v = *(const float4*)(g_G + (size_t)s * 128 + lane * 4);
    red_add_v4(g_ACC + (size_t)d * 128 + lane * 4, v);
}

// ------------------------------------------------------------------
// Finalize: X2 = relu(dinv * ACC + b)   (writes next layer input)
// ------------------------------------------------------------------
__global__ __launch_bounds__(256) void finalize_kernel(
    const float* __restrict__ b, int n)
{
    int idx = blockIdx.x * blockDim.x + threadIdx.x;  // over n*32 float4s
    if (idx >= n * 32) return;
    int row = idx >> 5;
    int c4 = idx & 31;
    float dv = g_dinv[row];
    size_t off = (size_t)row * 128 + c4 * 4;
    float4 a = *(const float4*)(g_ACC + off);
    float4 o;
    o.x = fmaxf(fmaf(dv, a.x, __ldg(&b[c4 * 4 + 0])), 0.0f);
    o.y = fmaxf(fmaf(dv, a.y, __ldg(&b[c4 * 4 + 1])), 0.0f);
    o.z = fmaxf(fmaf(dv, a.z, __ldg(&b[c4 * 4 + 2])), 0.0f);
    o.w = fmaxf(fmaf(dv, a.w, __ldg(&b[c4 * 4 + 3])), 0.0f);
    *(float4*)(g_X2 + off) = o;
}

// ------------------------------------------------------------------
// Output GEMM: out = X2 @ Wout + bout   (K=128, N=40)
// ------------------------------------------------------------------
__global__ __launch_bounds__(320) void out_gemm_kernel(
    const float* __restrict__ Wout, const float* __restrict__ bout,
    float* __restrict__ out, int n)
{
    __shared__ float Ws[128 * 40];
    __shared__ float Xs[32][132];
    __shared__ float bs[40];

    int tid = threadIdx.x;
    int row0 = blockIdx.x * 32;

    for (int idx = tid; idx < 128 * 40; idx += 320) Ws[idx] = Wout[idx];
    if (tid < 40) bs[tid] = bout[tid];
    for (int idx = tid; idx < 32 * 32; idx += 320) {
        int r = idx >> 5, k4 = idx & 31;
        int gr = row0 + r;
        float4 v = (gr < n) ? *(const float4*)(g_X2 + (size_t)gr * 128 + k4 * 4)
                            : make_float4(0.f, 0.f, 0.f, 0.f);
        *(float4*)(&Xs[r][k4 * 4]) = v;
    }
    __syncthreads();

    int col = tid % 40;
    int ty = tid / 40;   // 0..7
    float acc[4] = {0.f, 0.f, 0.f, 0.f};
#pragma unroll 4
    for (int k = 0; k < 128; k++) {
        float w = Ws[k * 40 + col];
#pragma unroll
        for (int r = 0; r < 4; r++)
            acc[r] = fmaf(Xs[ty + 8 * r][k], w, acc[r]);
    }
#pragma unroll
    for (int r = 0; r < 4; r++) {
        int row = row0 + ty + 8 * r;
        if (row < n) out[(size_t)row * 40 + col] = acc[r] + bs[col];
    }
}

// ------------------------------------------------------------------
// launch
// ------------------------------------------------------------------
extern "C" void kernel_launch(void* const* d_in, const int* in_sizes, int n_in,
                              void* d_out, int out_size)
{
    const float* x    = (const float*)d_in[0];
    const int*   ei   = (const int*)d_in[1];
    const float* W1   = (const float*)d_in[2];
    const float* b1   = (const float*)d_in[3];
    const float* W2   = (const float*)d_in[4];
    const float* b2   = (const float*)d_in[5];
    const float* Wout = (const float*)d_in[6];
    const float* bout = (const float*)d_in[7];
    float* out = (float*)d_out;

    int n = in_sizes[0] / 128;
    int e = in_sizes[1] / 2;
    const int* src = ei;
    const int* dst = ei + e;

    cudaFuncSetAttribute(gemm128_kernel,
                         cudaFuncAttributeMaxDynamicSharedMemorySize, GEMM_SMEM);

    int nb_n = (n + 255) / 256;
    int nb_e = (e + 255) / 256;
    int nb_gemm = (n + 63) / 64;
    long long edge_threads = (long long)e * 32;
    int nb_edge = (int)((edge_threads + 255) / 256);
    int nb_fin = (n * 32 + 255) / 256;
    int nb_out = (n + 31) / 32;

    // degrees (shared across both layers)
    zero_deg_kernel<<<nb_n, 256>>>(n);
    count_deg_kernel<<<nb_e, 256>>>(dst, e);
    calc_dinv_kernel<<<nb_n, 256>>>(n);

    // layer 1
    gemm128_kernel<<<nb_gemm, 256, GEMM_SMEM>>>(x, W1, n, 0);
    edge_agg_kernel<<<nb_edge, 256>>>(src, dst, e);
    finalize_kernel<<<nb_fin, 256>>>(b1, n);

    // layer 2
    gemm128_kernel<<<nb_gemm, 256, GEMM_SMEM>>>(nullptr, W2, n, 1);
    edge_agg_kernel<<<nb_edge, 256>>>(src, dst, e);
    finalize_kernel<<<nb_fin, 256>>>(b2, n);

    // output projection
    out_gemm_kernel<<<nb_out, 320>>>(Wout, bout, out, n);
}

// round 3
// speedup vs baseline: 2.6990x; 1.6348x over previous
#include <cuda_runtime.h>

#define NN 100000
#define EE 1600000
#define HD 128

// ---- device scratch (allocation-free contract: __device__ globals) ----
__device__ int   g_cnt[NN];       // in-degree counts
__device__ int   g_off[NN + 1];   // CSR offsets
__device__ int   g_cur[NN];       // scatter cursors
__device__ int   g_bsum[1024];    // block sums for scan
__device__ int   g_csr[EE];       // CSR column (src) indices
__device__ float g_dinv[NN];
__device__ float g_G[NN * HD];    // dinv-scaled features (messages)
__device__ float g_X2[NN * HD];   // layer output / next layer input

// ------------------------------------------------------------------
// CSR build
// ------------------------------------------------------------------
__global__ void zero_cnt_kernel(int n) {
    int i = blockIdx.x * blockDim.x + threadIdx.x;
    if (i < n) g_cnt[i] = 0;
}

__global__ void count_kernel(const int* __restrict__ dst, int e) {
    int i = blockIdx.x * blockDim.x + threadIdx.x;
    if (i < e) atomicAdd(&g_cnt[dst[i]], 1);
}

__global__ void dinv_kernel(int n) {
    int i = blockIdx.x * blockDim.x + threadIdx.x;
    if (i < n) g_dinv[i] = rsqrtf((float)g_cnt[i] + 1.0f);  // +1 self loop
}

// local exclusive scan: 1024 elements / block (256 threads x 4)
__global__ __launch_bounds__(256) void scan_local_kernel(int n) {
    __shared__ int ssum[256];
    int t = threadIdx.x;
    int base = blockIdx.x * 1024 + t * 4;
    int c0 = (base + 0 < n) ? g_cnt[base + 0] : 0;
    int c1 = (base + 1 < n) ? g_cnt[base + 1] : 0;
    int c2 = (base + 2 < n) ? g_cnt[base + 2] : 0;
    int c3 = (base + 3 < n) ? g_cnt[base + 3] : 0;
    int tsum = c0 + c1 + c2 + c3;
    ssum[t] = tsum;
    __syncthreads();
    for (int off = 1; off < 256; off <<= 1) {
        int v = (t >= off) ? ssum[t - off] : 0;
        __syncthreads();
        ssum[t] += v;
        __syncthreads();
    }
    int excl = ssum[t] - tsum;
    if (base + 0 < n) g_off[base + 0] = excl;
    if (base + 1 < n) g_off[base + 1] = excl + c0;
    if (base + 2 < n) g_off[base + 2] = excl + c0 + c1;
    if (base + 3 < n) g_off[base + 3] = excl + c0 + c1 + c2;
    if (t == 255) g_bsum[blockIdx.x] = ssum[255];
}

// scan of block sums (single block, up to 1024 blocks -> n <= 1M)
__global__ __launch_bounds__(1024) void scan_bsums_kernel(int nb) {
    __shared__ int s[1024];
    int t = threadIdx.x;
    int v = (t < nb) ? g_bsum[t] : 0;
    s[t] = v;
    __syncthreads();
    for (int off = 1; off < 1024; off <<= 1) {
        int u = (t >= off) ? s[t - off] : 0;
        __syncthreads();
        s[t] += u;
        __syncthreads();
    }
    if (t < nb) g_bsum[t] = s[t] - v;  // exclusive
}

__global__ void scan_add_kernel(int n, int e) {
    int i = blockIdx.x * blockDim.x + threadIdx.x;
    if (i < n) {
        int v = g_off[i] + g_bsum[i >> 10];
        g_off[i] = v;
        g_cur[i] = v;
    }
    if (i == 0) g_off[n] = e;
}

__global__ void scatter_kernel(const int* __restrict__ src,
                               const int* __restrict__ dst, int e) {
    int i = blockIdx.x * blockDim.x + threadIdx.x;
    if (i < e) {
        int pos = atomicAdd(&g_cur[dst[i]], 1);
        g_csr[pos] = src[i];
    }
}

// ------------------------------------------------------------------
// GEMM: G = (X @ W) * dinv[row]  (K=128, N=128)
// 64 rows/block, 256 threads, full K in shared. ~77% of fp32 FFMA peak.
// ------------------------------------------------------------------
#define GEMM_SMEM ((128 * 132 + 128 * 68) * 4)

__global__ __launch_bounds__(256) void gemm128_kernel(
    const float* __restrict__ Xext, const float* __restrict__ W,
    int n, int use_x2)
{
    extern __shared__ float sm[];
    float* Ws = sm;               // stride 132 floats
    float* Xt = sm + 128 * 132;   // stride 68 floats, [k][row]

    const float* X = use_x2 ? g_X2 : Xext;

    int tid = threadIdx.x;
    int row0 = blockIdx.x * 64;

    for (int idx = tid; idx < 128 * 32; idx += 256) {
        int r = idx >> 5, c4 = idx & 31;
        float4 v = *(const float4*)(W + r * 128 + c4 * 4);
        *(float4*)(Ws + r * 132 + c4 * 4) = v;
    }
    for (int idx = tid; idx < 64 * 32; idx += 256) {
        int r = idx >> 5, k4 = idx & 31;
        int grow = row0 + r;
        float4 v = (grow < n) ? *(const float4*)(X + (size_t)grow * 128 + k4 * 4)
                              : make_float4(0.f, 0.f, 0.f, 0.f);
        Xt[(k4 * 4 + 0) * 68 + r] = v.x;
        Xt[(k4 * 4 + 1) * 68 + r] = v.y;
        Xt[(k4 * 4 + 2) * 68 + r] = v.z;
        Xt[(k4 * 4 + 3) * 68 + r] = v.w;
    }
    __syncthreads();

    int tx = tid & 15;
    int ty = tid >> 4;

    float acc[4][8];
#pragma unroll
    for (int i = 0; i < 4; i++)
#pragma unroll
        for (int j = 0; j < 8; j++) acc[i][j] = 0.0f;

#pragma unroll 8
    for (int k = 0; k < 128; k++) {
        float4 a  = *(const float4*)(Xt + k * 68 + ty * 4);
        float4 b0 = *(const float4*)(Ws + k * 132 + tx * 4);
        float4 b1 = *(const float4*)(Ws + k * 132 + 64 + tx * 4);
        float av[4] = {a.x, a.y, a.z, a.w};
        float bv[8] = {b0.x, b0.y, b0.z, b0.w, b1.x, b1.y, b1.z, b1.w};
#pragma unroll
        for (int i = 0; i < 4; i++)
#pragma unroll
            for (int j = 0; j < 8; j++)
                acc[i][j] = fmaf(av[i], bv[j], acc[i][j]);
    }

#pragma unroll
    for (int i = 0; i < 4; i++) {
        int row = row0 + ty * 4 + i;
        if (row >= n) continue;
        float dv = g_dinv[row];
        float4 o0 = make_float4(acc[i][0] * dv, acc[i][1] * dv,
                                acc[i][2] * dv, acc[i][3] * dv);
        float4 o1 = make_float4(acc[i][4] * dv, acc[i][5] * dv,
                                acc[i][6] * dv, acc[i][7] * dv);
        size_t base = (size_t)row * 128;
        *(float4*)(g_G + base + tx * 4) = o0;
        *(float4*)(g_G + base + 64 + tx * 4) = o1;
    }
}

// ------------------------------------------------------------------
// Fused CSR gather-reduce + finalize:
// X2[d] = relu(dinv[d] * (G[d] + sum_{s in N(d)} G[s]) + b)
// One warp per dst node; lane covers 4 consecutive floats.
// ------------------------------------------------------------------
__global__ __launch_bounds__(256) void agg_fin_kernel(
    const float* __restrict__ b, int n)
{
    int gid = blockIdx.x * blockDim.x + threadIdx.x;
    int node = gid >> 5;
    int lane = gid & 31;
    if (node >= n) return;

    int beg = g_off[node];
    int end = g_off[node + 1];
    size_t loff = (size_t)lane * 4;

    // self contribution
    float4 acc = *(const float4*)(g_G + (size_t)node * 128 + loff);

    int j = beg;
    for (; j + 4 <= end; j += 4) {
        int s0 = g_csr[j + 0];
        int s1 = g_csr[j + 1];
        int s2 = g_csr[j + 2];
        int s3 = g_csr[j + 3];
        float4 v0 = *(const float4*)(g_G + (size_t)s0 * 128 + loff);
        float4 v1 = *(const float4*)(g_G + (size_t)s1 * 128 + loff);
        float4 v2 = *(const float4*)(g_G + (size_t)s2 * 128 + loff);
        float4 v3 = *(const float4*)(g_G + (size_t)s3 * 128 + loff);
        acc.x += v0.x + v1.x + v2.x + v3.x;
        acc.y += v0.y + v1.y + v2.y + v3.y;
        acc.z += v0.z + v1.z + v2.z + v3.z;
        acc.w += v0.w + v1.w + v2.w + v3.w;
    }
    for (; j < end; j++) {
        int s = g_csr[j];
        float4 v = *(const float4*)(g_G + (size_t)s * 128 + loff);
        acc.x += v.x; acc.y += v.y; acc.z += v.z; acc.w += v.w;
    }

    float dv = g_dinv[node];
    float4 bb = *(const float4*)(b + lane * 4);
    float4 o;
    o.x = fmaxf(fmaf(dv, acc.x, bb.x), 0.0f);
    o.y = fmaxf(fmaf(dv, acc.y, bb.y), 0.0f);
    o.z = fmaxf(fmaf(dv, acc.z, bb.z), 0.0f);
    o.w = fmaxf(fmaf(dv, acc.w, bb.w), 0.0f);
    *(float4*)(g_X2 + (size_t)node * 128 + loff) = o;
}

// ------------------------------------------------------------------
// Output GEMM: out = X2 @ Wout + bout   (K=128, N=40)
// ------------------------------------------------------------------
__global__ __launch_bounds__(320) void out_gemm_kernel(
    const float* __restrict__ Wout, const float* __restrict__ bout,
    float* __restrict__ out, int n)
{
    __shared__ float Ws[128 * 40];
    __shared__ float Xs[32][132];
    __shared__ float bs[40];

    int tid = threadIdx.x;
    int row0 = blockIdx.x * 32;

    for (int idx = tid; idx < 128 * 40; idx += 320) Ws[idx] = Wout[idx];
    if (tid < 40) bs[tid] = bout[tid];
    for (int idx = tid; idx < 32 * 32; idx += 320) {
        int r = idx >> 5, k4 = idx & 31;
        int gr = row0 + r;
        float4 v = (gr < n) ? *(const float4*)(g_X2 + (size_t)gr * 128 + k4 * 4)
                            : make_float4(0.f, 0.f, 0.f, 0.f);
        *(float4*)(&Xs[r][k4 * 4]) = v;
    }
    __syncthreads();

    int col = tid % 40;
    int ty = tid / 40;   // 0..7
    float acc[4] = {0.f, 0.f, 0.f, 0.f};
#pragma unroll 4
    for (int k = 0; k < 128; k++) {
        float w = Ws[k * 40 + col];
#pragma unroll
        for (int r = 0; r < 4; r++)
            acc[r] = fmaf(Xs[ty + 8 * r][k], w, acc[r]);
    }
#pragma unroll
    for (int r = 0; r < 4; r++) {
        int row = row0 + ty + 8 * r;
        if (row < n) out[(size_t)row * 40 + col] = acc[r] + bs[col];
    }
}

// ------------------------------------------------------------------
// launch
// ------------------------------------------------------------------
extern "C" void kernel_launch(void* const* d_in, const int* in_sizes, int n_in,
                              void* d_out, int out_size)
{
    const float* x    = (const float*)d_in[0];
    const int*   ei   = (const int*)d_in[1];
    const float* W1   = (const float*)d_in[2];
    const float* b1   = (const float*)d_in[3];
    const float* W2   = (const float*)d_in[4];
    const float* b2   = (const float*)d_in[5];
    const float* Wout = (const float*)d_in[6];
    const float* bout = (const float*)d_in[7];
    float* out = (float*)d_out;

    int n = in_sizes[0] / 128;
    int e = in_sizes[1] / 2;
    const int* src = ei;
    const int* dst = ei + e;

    cudaFuncSetAttribute(gemm128_kernel,
                         cudaFuncAttributeMaxDynamicSharedMemorySize, GEMM_SMEM);

    int nb_n = (n + 255) / 256;
    int nb_e = (e + 255) / 256;
    int nb_gemm = (n + 63) / 64;
    int nb_scan = (n + 1023) / 1024;
    long long agg_threads = (long long)n * 32;
    int nb_agg = (int)((agg_threads + 255) / 256);
    int nb_out = (n + 31) / 32;

    // CSR build (shared across both layers)
    zero_cnt_kernel<<<nb_n, 256>>>(n);
    count_kernel<<<nb_e, 256>>>(dst, e);
    dinv_kernel<<<nb_n, 256>>>(n);
    scan_local_kernel<<<nb_scan, 256>>>(n);
    scan_bsums_kernel<<<1, 1024>>>(nb_scan);
    scan_add_kernel<<<nb_n, 256>>>(n, e);
    scatter_kernel<<<nb_e, 256>>>(src, dst, e);

    // layer 1
    gemm128_kernel<<<nb_gemm, 256, GEMM_SMEM>>>(x, W1, n, 0);
    agg_fin_kernel<<<nb_agg, 256>>>(b1, n);

    // layer 2
    gemm128_kernel<<<nb_gemm, 256, GEMM_SMEM>>>(nullptr, W2, n, 1);
    agg_fin_kernel<<<nb_agg, 256>>>(b2, n);

    // output projection
    out_gemm_kernel<<<nb_out, 320>>>(Wout, bout, out, n);
}

// round 7
// speedup vs baseline: 3.0370x; 1.1253x over previous
#include <cuda_runtime.h>
#include <cstdint>

#define NN 100000
#define EE 1600000

// ---- device scratch ----
__device__ int   g_cnt[NN];
__device__ int   g_off[NN + 1];
__device__ int   g_cur[NN];
__device__ int   g_bsum[1024];
__device__ int   g_csr[EE];
__device__ float g_dinv[NN];
__device__ float g_G[NN * 128];
__device__ float g_X2[NN * 128];

// ------------------------------------------------------------------
// CSR build
// ------------------------------------------------------------------
__global__ void zero_cnt_kernel(int n) {
    int i = blockIdx.x * blockDim.x + threadIdx.x;
    if (i < n) g_cnt[i] = 0;
}
__global__ void count_kernel(const int* __restrict__ dst, int e) {
    int i = blockIdx.x * blockDim.x + threadIdx.x;
    if (i < e) atomicAdd(&g_cnt[dst[i]], 1);
}
__global__ void dinv_kernel(int n) {
    int i = blockIdx.x * blockDim.x + threadIdx.x;
    if (i < n) g_dinv[i] = rsqrtf((float)g_cnt[i] + 1.0f);
}
__global__ __launch_bounds__(256) void scan_local_kernel(int n) {
    __shared__ int ssum[256];
    int t = threadIdx.x;
    int base = blockIdx.x * 1024 + t * 4;
    int c0 = (base + 0 < n) ? g_cnt[base + 0] : 0;
    int c1 = (base + 1 < n) ? g_cnt[base + 1] : 0;
    int c2 = (base + 2 < n) ? g_cnt[base + 2] : 0;
    int c3 = (base + 3 < n) ? g_cnt[base + 3] : 0;
    int tsum = c0 + c1 + c2 + c3;
    ssum[t] = tsum;
    __syncthreads();
    for (int off = 1; off < 256; off <<= 1) {
        int v = (t >= off) ? ssum[t - off] : 0;
        __syncthreads();
        ssum[t] += v;
        __syncthreads();
    }
    int excl = ssum[t] - tsum;
    if (base + 0 < n) g_off[base + 0] = excl;
    if (base + 1 < n) g_off[base + 1] = excl + c0;
    if (base + 2 < n) g_off[base + 2] = excl + c0 + c1;
    if (base + 3 < n) g_off[base + 3] = excl + c0 + c1 + c2;
    if (t == 255) g_bsum[blockIdx.x] = ssum[255];
}
__global__ __launch_bounds__(1024) void scan_bsums_kernel(int nb) {
    __shared__ int s[1024];
    int t = threadIdx.x;
    int v = (t < nb) ? g_bsum[t] : 0;
    s[t] = v;
    __syncthreads();
    for (int off = 1; off < 1024; off <<= 1) {
        int u = (t >= off) ? s[t - off] : 0;
        __syncthreads();
        s[t] += u;
        __syncthreads();
    }
    if (t < nb) g_bsum[t] = s[t] - v;
}
__global__ void scan_add_kernel(int n, int e) {
    int i = blockIdx.x * blockDim.x + threadIdx.x;
    if (i < n) {
        int v = g_off[i] + g_bsum[i >> 10];
        g_off[i] = v;
        g_cur[i] = v;
    }
    if (i == 0) g_off[n] = e;
}
__global__ void scatter_kernel(const int* __restrict__ src,
                               const int* __restrict__ dst, int e) {
    int i = blockIdx.x * blockDim.x + threadIdx.x;
    if (i < e) {
        int pos = atomicAdd(&g_cur[dst[i]], 1);
        g_csr[pos] = src[i];
    }
}

// ------------------------------------------------------------------
// tf32 mma.sync GEMM (sm_80-compatible PTX; runs on tensor pipe)
// ------------------------------------------------------------------
__device__ __forceinline__ uint32_t cvt_tf32(float x) {
    uint32_t r;
    asm("cvt.rna.tf32.f32 %0, %1;" : "=r"(r) : "f"(x));
    return r;
}
__device__ __forceinline__ void mma8(float* d, const uint32_t* a, const uint32_t* b) {
    asm volatile(
        "mma.sync.aligned.m16n8k8.row.col.f32.tf32.tf32.f32 "
        "{%0,%1,%2,%3}, {%4,%5,%6,%7}, {%8,%9}, {%0,%1,%2,%3};"
        : "+f"(d[0]), "+f"(d[1]), "+f"(d[2]), "+f"(d[3])
        : "r"(a[0]), "r"(a[1]), "r"(a[2]), "r"(a[3]), "r"(b[0]), "r"(b[1]));
}

// smem (floats): Bhi[128*132], Blo[128*132], Ahi[128*68], Alo[128*68]
#define OFF_BHI 0
#define OFF_BLO 16896
#define OFF_AHI 33792
#define OFF_ALO 42496
#define GEMM_SMEM_FL 51200
#define GEMM_SMEM_B (GEMM_SMEM_FL * 4)

// G = (X @ W) * dinv[row]; persistent; M-tile 128, N=128, K=128 (2 chunks of 64)
__global__ __launch_bounds__(256) void gemm_mma_kernel(
    const float* __restrict__ Xext, const float* __restrict__ W,
    int n, int use_x2)
{
    extern __shared__ float sm[];
    const float* X = use_x2 ? g_X2 : Xext;
    int tid = threadIdx.x, w = tid >> 5, lane = tid & 31;
    int g = lane >> 2, t4 = lane & 3;

    // fill W hi/lo once: Bs[n][k] = W[k][n], stride 132
    for (int i = tid; i < 128 * 128; i += 256) {
        int k = i >> 7, nn2 = i & 127;
        float wv = W[i];
        uint32_t hi = cvt_tf32(wv);
        uint32_t lo = cvt_tf32(wv - __uint_as_float(hi));
        sm[OFF_BHI + nn2 * 132 + k] = __uint_as_float(hi);
        sm[OFF_BLO + nn2 * 132 + k] = __uint_as_float(lo);
    }
    __syncthreads();

    int rb = (w >> 1) * 32;       // warp row base (0,32,64,96)
    int cb = (w & 1) * 64;        // warp col base (0,64)

    int ntiles = (n + 127) >> 7;
    for (int t = blockIdx.x; t < ntiles; t += gridDim.x) {
        int trow = t << 7;

        float acc[2][8][4];
#pragma unroll
        for (int mi = 0; mi < 2; mi++)
#pragma unroll
            for (int ni = 0; ni < 8; ni++)
#pragma unroll
                for (int j = 0; j < 4; j++) acc[mi][ni][j] = 0.0f;

        for (int c = 0; c < 2; c++) {
            // fill A chunk hi/lo: As[m][kk], kk in [0,64), stride 68
            for (int i4 = tid; i4 < 128 * 16; i4 += 256) {
                int m = i4 >> 4, q = i4 & 15;
                int row = trow + m;
                float4 v = make_float4(0.f, 0.f, 0.f, 0.f);
                if (row < n)
                    v = *(const float4*)(X + (size_t)row * 128 + c * 64 + q * 4);
                uint32_t h0 = cvt_tf32(v.x), h1 = cvt_tf32(v.y);
                uint32_t h2 = cvt_tf32(v.z), h3 = cvt_tf32(v.w);
                float* ah = sm + OFF_AHI + m * 68 + q * 4;
                float* al = sm + OFF_ALO + m * 68 + q * 4;
                ah[0] = __uint_as_float(h0); ah[1] = __uint_as_float(h1);
                ah[2] = __uint_as_float(h2); ah[3] = __uint_as_float(h3);
                al[0] = v.x - __uint_as_float(h0);
                al[1] = v.y - __uint_as_float(h1);
                al[2] = v.z - __uint_as_float(h2);
                al[3] = v.w - __uint_as_float(h3);
            }
            // note: lo stored as f32 then converted on load? No — convert here:
            __syncthreads();
            // convert lo in place to tf32 (second pass, cheap)
            for (int i = tid; i < 128 * 17; i += 256) {
                // covers stride-68 rows incl. pad; only convert real cols
                int m = i / 17, q4 = i % 17;
                if (q4 < 16) {
                    float* al = sm + OFF_ALO + m * 68 + q4 * 4;
                    al[0] = __uint_as_float(cvt_tf32(al[0]));
                    al[1] = __uint_as_float(cvt_tf32(al[1]));
                    al[2] = __uint_as_float(cvt_tf32(al[2]));
                    al[3] = __uint_as_float(cvt_tf32(al[3]));
                }
            }
            __syncthreads();

            for (int kb = 0; kb < 8; kb++) {
                int kk = kb * 8 + t4;          // chunk-local A col
                int kB = c * 64 + kb * 8 + t4; // absolute B col
                uint32_t ah[2][4], al[2][4];
#pragma unroll
                for (int mi = 0; mi < 2; mi++) {
                    int r0 = rb + mi * 16 + g;
                    const float* basep = sm + OFF_AHI + r0 * 68 + kk;
                    ah[mi][0] = __float_as_uint(basep[0]);
                    ah[mi][1] = __float_as_uint(basep[8 * 68]);
                    ah[mi][2] = __float_as_uint(basep[4]);
                    ah[mi][3] = __float_as_uint(basep[8 * 68 + 4]);
                    const float* basel = sm + OFF_ALO + r0 * 68 + kk;
                    al[mi][0] = __float_as_uint(basel[0]);
                    al[mi][1] = __float_as_uint(basel[8 * 68]);
                    al[mi][2] = __float_as_uint(basel[4]);
                    al[mi][3] = __float_as_uint(basel[8 * 68 + 4]);
                }
#pragma unroll
                for (int ni = 0; ni < 8; ni++) {
                    int nidx = cb + ni * 8 + g;
                    uint32_t bh[2], bl[2];
                    const float* bph = sm + OFF_BHI + nidx * 132 + kB;
                    const float* bpl = sm + OFF_BLO + nidx * 132 + kB;
                    bh[0] = __float_as_uint(bph[0]);
                    bh[1] = __float_as_uint(bph[4]);
                    bl[0] = __float_as_uint(bpl[0]);
                    bl[1] = __float_as_uint(bpl[4]);
#pragma unroll
                    for (int mi = 0; mi < 2; mi++) {
                        mma8(acc[mi][ni], ah[mi], bh);
                        mma8(acc[mi][ni], ah[mi], bl);
                        mma8(acc[mi][ni], al[mi], bh);
                    }
                }
            }
            __syncthreads();
        }

        // epilogue: acc * dinv -> g_G
#pragma unroll
        for (int mi = 0; mi < 2; mi++) {
            int r0 = trow + rb + mi * 16 + g;
            int r1 = r0 + 8;
            float dv0 = (r0 < n) ? g_dinv[r0] : 0.f;
            float dv1 = (r1 < n) ? g_dinv[r1] : 0.f;
#pragma unroll
            for (int ni = 0; ni < 8; ni++) {
                int col = cb + ni * 8 + t4 * 2;
                if (r0 < n) {
                    float2 o = make_float2(acc[mi][ni][0] * dv0,
                                           acc[mi][ni][1] * dv0);
                    *(float2*)(g_G + (size_t)r0 * 128 + col) = o;
                }
                if (r1 < n) {
                    float2 o = make_float2(acc[mi][ni][2] * dv1,
                                           acc[mi][ni][3] * dv1);
                    *(float2*)(g_G + (size_t)r1 * 128 + col) = o;
                }
            }
        }
        __syncthreads();
    }
}

// ------------------------------------------------------------------
// Fused CSR gather-reduce + finalize
// ------------------------------------------------------------------
__global__ __launch_bounds__(256) void agg_fin_kernel(
    const float* __restrict__ b, int n)
{
    int gid = blockIdx.x * blockDim.x + threadIdx.x;
    int node = gid >> 5;
    int lane = gid & 31;
    if (node >= n) return;

    int beg = g_off[node];
    int end = g_off[node + 1];
    size_t loff = (size_t)lane * 4;

    float4 acc = *(const float4*)(g_G + (size_t)node * 128 + loff);

    int j = beg;
    for (; j + 4 <= end; j += 4) {
        int s0 = g_csr[j + 0];
        int s1 = g_csr[j + 1];
        int s2 = g_csr[j + 2];
        int s3 = g_csr[j + 3];
        float4 v0 = *(const float4*)(g_G + (size_t)s0 * 128 + loff);
        float4 v1 = *(const float4*)(g_G + (size_t)s1 * 128 + loff);
        float4 v2 = *(const float4*)(g_G + (size_t)s2 * 128 + loff);
        float4 v3 = *(const float4*)(g_G + (size_t)s3 * 128 + loff);
        acc.x += v0.x + v1.x + v2.x + v3.x;
        acc.y += v0.y + v1.y + v2.y + v3.y;
        acc.z += v0.z + v1.z + v2.z + v3.z;
        acc.w += v0.w + v1.w + v2.w + v3.w;
    }
    for (; j < end; j++) {
        int s = g_csr[j];
        float4 v = *(const float4*)(g_G + (size_t)s * 128 + loff);
        acc.x += v.x; acc.y += v.y; acc.z += v.z; acc.w += v.w;
    }

    float dv = g_dinv[node];
    float4 bb = *(const float4*)(b + lane * 4);
    float4 o;
    o.x = fmaxf(fmaf(dv, acc.x, bb.x), 0.0f);
    o.y = fmaxf(fmaf(dv, acc.y, bb.y), 0.0f);
    o.z = fmaxf(fmaf(dv, acc.z, bb.z), 0.0f);
    o.w = fmaxf(fmaf(dv, acc.w, bb.w), 0.0f);
    *(float4*)(g_X2 + (size_t)node * 128 + loff) = o;
}

// ------------------------------------------------------------------
// Output GEMM: out = X2 @ Wout + bout   (K=128, N=40)
// ------------------------------------------------------------------
__global__ __launch_bounds__(320) void out_gemm_kernel(
    const float* __restrict__ Wout, const float* __restrict__ bout,
    float* __restrict__ out, int n)
{
    __shared__ float Ws[128 * 40];
    __shared__ float Xs[32][132];
    __shared__ float bs[40];

    int tid = threadIdx.x;
    int row0 = blockIdx.x * 32;

    for (int idx = tid; idx < 128 * 40; idx += 320) Ws[idx] = Wout[idx];
    if (tid < 40) bs[tid] = bout[tid];
    for (int idx = tid; idx < 32 * 32; idx += 320) {
        int r = idx >> 5, k4 = idx & 31;
        int gr = row0 + r;
        float4 v = (gr < n) ? *(const float4*)(g_X2 + (size_t)gr * 128 + k4 * 4)
                            : make_float4(0.f, 0.f, 0.f, 0.f);
        *(float4*)(&Xs[r][k4 * 4]) = v;
    }
    __syncthreads();

    int col = tid % 40;
    int ty = tid / 40;
    float acc[4] = {0.f, 0.f, 0.f, 0.f};
#pragma unroll 4
    for (int k = 0; k < 128; k++) {
        float w = Ws[k * 40 + col];
#pragma unroll
        for (int r = 0; r < 4; r++)
            acc[r] = fmaf(Xs[ty + 8 * r][k], w, acc[r]);
    }
#pragma unroll
    for (int r = 0; r < 4; r++) {
        int row = row0 + ty + 8 * r;
        if (row < n) out[(size_t)row * 40 + col] = acc[r] + bs[col];
    }
}

// ------------------------------------------------------------------
// launch
// ------------------------------------------------------------------
extern "C" void kernel_launch(void* const* d_in, const int* in_sizes, int n_in,
                              void* d_out, int out_size)
{
    const float* x    = (const float*)d_in[0];
    const int*   ei   = (const int*)d_in[1];
    const float* W1   = (const float*)d_in[2];
    const float* b1   = (const float*)d_in[3];
    const float* W2   = (const float*)d_in[4];
    const float* b2   = (const float*)d_in[5];
    const float* Wout = (const float*)d_in[6];
    const float* bout = (const float*)d_in[7];
    float* out = (float*)d_out;

    int n = in_sizes[0] / 128;
    int e = in_sizes[1] / 2;
    const int* src = ei;
    const int* dst = ei + e;

    cudaFuncSetAttribute(gemm_mma_kernel,
                         cudaFuncAttributeMaxDynamicSharedMemorySize, GEMM_SMEM_B);

    int nb_n = (n + 255) / 256;
    int nb_e = (e + 255) / 256;
    int nb_scan = (n + 1023) / 1024;
    long long agg_threads = (long long)n * 32;
    int nb_agg = (int)((agg_threads + 255) / 256);
    int nb_out = (n + 31) / 32;

    // CSR build (shared across both layers)
    zero_cnt_kernel<<<nb_n, 256>>>(n);
    count_kernel<<<nb_e, 256>>>(dst, e);
    dinv_kernel<<<nb_n, 256>>>(n);
    scan_local_kernel<<<nb_scan, 256>>>(n);
    scan_bsums_kernel<<<1, 1024>>>(nb_scan);
    scan_add_kernel<<<nb_n, 256>>>(n, e);
    scatter_kernel<<<nb_e, 256>>>(src, dst, e);

    // layer 1
    gemm_mma_kernel<<<152, 256, GEMM_SMEM_B>>>(x, W1, n, 0);
    agg_fin_kernel<<<nb_agg, 256>>>(b1, n);

    // layer 2
    gemm_mma_kernel<<<152, 256, GEMM_SMEM_B>>>(nullptr, W2, n, 1);
    agg_fin_kernel<<<nb_agg, 256>>>(b2, n);

    // output projection
    out_gemm_kernel<<<nb_out, 320>>>(Wout, bout, out, n);
}

// round 9
// speedup vs baseline: 3.3828x; 1.1139x over previous
#include <cuda_runtime.h>
#include <cstdint>

#define NN 100000
#define EE 1600000

// ---- device scratch ----
__device__ int   g_cnt[NN];
__device__ int   g_off[NN + 1];
__device__ int   g_cur[NN];
__device__ int   g_bsum[1024];
__device__ int   g_csr[EE];
__device__ float g_dinv[NN];
__device__ float g_G[NN * 128];
__device__ float g_X2[NN * 128];

// ------------------------------------------------------------------
// CSR build
// ------------------------------------------------------------------
__global__ void zero_cnt_kernel(int n) {
    int i = blockIdx.x * blockDim.x + threadIdx.x;
    if (i < n) g_cnt[i] = 0;
}
__global__ void count_kernel(const int* __restrict__ dst, int e) {
    int i = blockIdx.x * blockDim.x + threadIdx.x;
    if (i < e) atomicAdd(&g_cnt[dst[i]], 1);
}
__global__ void dinv_kernel(int n) {
    int i = blockIdx.x * blockDim.x + threadIdx.x;
    if (i < n) g_dinv[i] = rsqrtf((float)g_cnt[i] + 1.0f);
}
__global__ __launch_bounds__(256) void scan_local_kernel(int n) {
    __shared__ int ssum[256];
    int t = threadIdx.x;
    int base = blockIdx.x * 1024 + t * 4;
    int c0 = (base + 0 < n) ? g_cnt[base + 0] : 0;
    int c1 = (base + 1 < n) ? g_cnt[base + 1] : 0;
    int c2 = (base + 2 < n) ? g_cnt[base + 2] : 0;
    int c3 = (base + 3 < n) ? g_cnt[base + 3] : 0;
    int tsum = c0 + c1 + c2 + c3;
    ssum[t] = tsum;
    __syncthreads();
    for (int off = 1; off < 256; off <<= 1) {
        int v = (t >= off) ? ssum[t - off] : 0;
        __syncthreads();
        ssum[t] += v;
        __syncthreads();
    }
    int excl = ssum[t] - tsum;
    if (base + 0 < n) g_off[base + 0] = excl;
    if (base + 1 < n) g_off[base + 1] = excl + c0;
    if (base + 2 < n) g_off[base + 2] = excl + c0 + c1;
    if (base + 3 < n) g_off[base + 3] = excl + c0 + c1 + c2;
    if (t == 255) g_bsum[blockIdx.x] = ssum[255];
}
__global__ __launch_bounds__(1024) void scan_bsums_kernel(int nb) {
    __shared__ int s[1024];
    int t = threadIdx.x;
    int v = (t < nb) ? g_bsum[t] : 0;
    s[t] = v;
    __syncthreads();
    for (int off = 1; off < 1024; off <<= 1) {
        int u = (t >= off) ? s[t - off] : 0;
        __syncthreads();
        s[t] += u;
        __syncthreads();
    }
    if (t < nb) g_bsum[t] = s[t] - v;
}
__global__ void scan_add_kernel(int n, int e) {
    int i = blockIdx.x * blockDim.x + threadIdx.x;
    if (i < n) {
        int v = g_off[i] + g_bsum[i >> 10];
        g_off[i] = v;
        g_cur[i] = v;
    }
    if (i == 0) g_off[n] = e;
}
__global__ void scatter_kernel(const int* __restrict__ src,
                               const int* __restrict__ dst, int e) {
    int i = blockIdx.x * blockDim.x + threadIdx.x;
    if (i < e) {
        int pos = atomicAdd(&g_cur[dst[i]], 1);
        g_csr[pos] = src[i];
    }
}

// ------------------------------------------------------------------
// tf32 mma.sync GEMM (sm_80-compatible PTX; runs on tensor pipe)
// ------------------------------------------------------------------
__device__ __forceinline__ uint32_t cvt_tf32(float x) {
    uint32_t r;
    asm("cvt.rna.tf32.f32 %0, %1;" : "=r"(r) : "f"(x));
    return r;
}
__device__ __forceinline__ void mma8(float* d, const uint32_t* a, const uint32_t* b) {
    asm volatile(
        "mma.sync.aligned.m16n8k8.row.col.f32.tf32.tf32.f32 "
        "{%0,%1,%2,%3}, {%4,%5,%6,%7}, {%8,%9}, {%0,%1,%2,%3};"
        : "+f"(d[0]), "+f"(d[1]), "+f"(d[2]), "+f"(d[3])
        : "r"(a[0]), "r"(a[1]), "r"(a[2]), "r"(a[3]), "r"(b[0]), "r"(b[1]));
}

// smem (floats): Bhi[128*132], Blo[128*132], Ahi[128*68], Alo[128*68]
#define OFF_BHI 0
#define OFF_BLO 16896
#define OFF_AHI 33792
#define OFF_ALO 42496
#define GEMM_SMEM_FL 51200
#define GEMM_SMEM_B (GEMM_SMEM_FL * 4)

// load one A chunk (K=64 cols starting at c*64) into 8 float4 regs
__device__ __forceinline__ void load_A_regs(
    const float* __restrict__ X, int trow, int c, int n, int tid, float4* va)
{
#pragma unroll
    for (int j = 0; j < 8; j++) {
        int i4 = tid + j * 256;
        int m = i4 >> 4, q = i4 & 15;
        int row = trow + m;
        va[j] = make_float4(0.f, 0.f, 0.f, 0.f);
        if (row < n)
            va[j] = *(const float4*)(X + (size_t)row * 128 + c * 64 + q * 4);
    }
}

// convert regs -> tf32 hi/lo and store to smem A buffers (stride 68)
__device__ __forceinline__ void store_A_smem(float* sm, int tid, const float4* va)
{
#pragma unroll
    for (int j = 0; j < 8; j++) {
        int i4 = tid + j * 256;
        int m = i4 >> 4, q = i4 & 15;
        float4 v = va[j];
        uint32_t h0 = cvt_tf32(v.x), h1 = cvt_tf32(v.y);
        uint32_t h2 = cvt_tf32(v.z), h3 = cvt_tf32(v.w);
        uint32_t l0 = cvt_tf32(v.x - __uint_as_float(h0));
        uint32_t l1 = cvt_tf32(v.y - __uint_as_float(h1));
        uint32_t l2 = cvt_tf32(v.z - __uint_as_float(h2));
        uint32_t l3 = cvt_tf32(v.w - __uint_as_float(h3));
        float* ah = sm + OFF_AHI + m * 68 + q * 4;
        float* al = sm + OFF_ALO + m * 68 + q * 4;
        ah[0] = __uint_as_float(h0); ah[1] = __uint_as_float(h1);
        ah[2] = __uint_as_float(h2); ah[3] = __uint_as_float(h3);
        al[0] = __uint_as_float(l0); al[1] = __uint_as_float(l1);
        al[2] = __uint_as_float(l2); al[3] = __uint_as_float(l3);
    }
}

// G = (X @ W) * dinv[row]; persistent; M-tile 128, N=128, K=128 (2 chunks of 64)
__global__ __launch_bounds__(256) void gemm_mma_kernel(
    const float* __restrict__ Xext, const float* __restrict__ W,
    int n, int use_x2)
{
    extern __shared__ float sm[];
    const float* X = use_x2 ? g_X2 : Xext;
    int tid = threadIdx.x, w = tid >> 5, lane = tid & 31;
    int g = lane >> 2, t4 = lane & 3;

    // fill W hi/lo once: Bs[n][k] = W[k][n], stride 132
    for (int i = tid; i < 128 * 128; i += 256) {
        int k = i >> 7, nn2 = i & 127;
        float wv = W[i];
        uint32_t hi = cvt_tf32(wv);
        uint32_t lo = cvt_tf32(wv - __uint_as_float(hi));
        sm[OFF_BHI + nn2 * 132 + k] = __uint_as_float(hi);
        sm[OFF_BLO + nn2 * 132 + k] = __uint_as_float(lo);
    }

    int rb = (w >> 1) * 32;       // warp row base (0,32,64,96)
    int cb = (w & 1) * 64;        // warp col base (0,64)
    int ntiles = (n + 127) >> 7;
    int stride = gridDim.x;

    float4 va[8];
    int t = blockIdx.x;
    if (t < ntiles) load_A_regs(X, t << 7, 0, n, tid, va);
    __syncthreads();   // W fill complete (covers first store too)

    for (; t < ntiles; t += stride) {
        int trow = t << 7;

        float acc[2][8][4];
#pragma unroll
        for (int mi = 0; mi < 2; mi++)
#pragma unroll
            for (int ni = 0; ni < 8; ni++)
#pragma unroll
                for (int j = 0; j < 4; j++) acc[mi][ni][j] = 0.0f;

#pragma unroll
        for (int c = 0; c < 2; c++) {
            // store prefetched A chunk into smem (convert to tf32 hi/lo)
            store_A_smem(sm, tid, va);
            __syncthreads();

            // prefetch next chunk (this tile's chunk 1, or next tile's chunk 0)
            int tn = (c == 0) ? t : t + stride;
            int cn = c ^ 1;
            if (tn < ntiles) load_A_regs(X, tn << 7, cn, n, tid, va);

            // compute chunk c
#pragma unroll 2
            for (int kb = 0; kb < 8; kb++) {
                int kk = kb * 8 + t4;          // chunk-local A col
                int kB = c * 64 + kb * 8 + t4; // absolute B col
                uint32_t ah[2][4], al[2][4];
#pragma unroll
                for (int mi = 0; mi < 2; mi++) {
                    int r0 = rb + mi * 16 + g;
                    const float* basep = sm + OFF_AHI + r0 * 68 + kk;
                    ah[mi][0] = __float_as_uint(basep[0]);
                    ah[mi][1] = __float_as_uint(basep[8 * 68]);
                    ah[mi][2] = __float_as_uint(basep[4]);
                    ah[mi][3] = __float_as_uint(basep[8 * 68 + 4]);
                    const float* basel = sm + OFF_ALO + r0 * 68 + kk;
                    al[mi][0] = __float_as_uint(basel[0]);
                    al[mi][1] = __float_as_uint(basel[8 * 68]);
                    al[mi][2] = __float_as_uint(basel[4]);
                    al[mi][3] = __float_as_uint(basel[8 * 68 + 4]);
                }
#pragma unroll
                for (int ni = 0; ni < 8; ni++) {
                    int nidx = cb + ni * 8 + g;
                    uint32_t bh[2], bl[2];
                    const float* bph = sm + OFF_BHI + nidx * 132 + kB;
                    const float* bpl = sm + OFF_BLO + nidx * 132 + kB;
                    bh[0] = __float_as_uint(bph[0]);
                    bh[1] = __float_as_uint(bph[4]);
                    bl[0] = __float_as_uint(bpl[0]);
                    bl[1] = __float_as_uint(bpl[4]);
#pragma unroll
                    for (int mi = 0; mi < 2; mi++) {
                        mma8(acc[mi][ni], ah[mi], bh);
                        mma8(acc[mi][ni], ah[mi], bl);
                        mma8(acc[mi][ni], al[mi], bh);
                    }
                }
            }
            __syncthreads();
        }

        // epilogue: acc * dinv -> g_G
#pragma unroll
        for (int mi = 0; mi < 2; mi++) {
            int r0 = trow + rb + mi * 16 + g;
            int r1 = r0 + 8;
            float dv0 = (r0 < n) ? g_dinv[r0] : 0.f;
            float dv1 = (r1 < n) ? g_dinv[r1] : 0.f;
#pragma unroll
            for (int ni = 0; ni < 8; ni++) {
                int col = cb + ni * 8 + t4 * 2;
                if (r0 < n) {
                    float2 o = make_float2(acc[mi][ni][0] * dv0,
                                           acc[mi][ni][1] * dv0);
                    *(float2*)(g_G + (size_t)r0 * 128 + col) = o;
                }
                if (r1 < n) {
                    float2 o = make_float2(acc[mi][ni][2] * dv1,
                                           acc[mi][ni][3] * dv1);
                    *(float2*)(g_G + (size_t)r1 * 128 + col) = o;
                }
            }
        }
    }
}

// ------------------------------------------------------------------
// Fused CSR gather-reduce + finalize
// ------------------------------------------------------------------
__global__ __launch_bounds__(256) void agg_fin_kernel(
    const float* __restrict__ b, int n)
{
    int gid = blockIdx.x * blockDim.x + threadIdx.x;
    int node = gid >> 5;
    int lane = gid & 31;
    if (node >= n) return;

    int beg = g_off[node];
    int end = g_off[node + 1];
    size_t loff = (size_t)lane * 4;

    float4 acc = *(const float4*)(g_G + (size_t)node * 128 + loff);

    int j = beg;
    for (; j + 4 <= end; j += 4) {
        int s0 = g_csr[j + 0];
        int s1 = g_csr[j + 1];
        int s2 = g_csr[j + 2];
        int s3 = g_csr[j + 3];
        float4 v0 = *(const float4*)(g_G + (size_t)s0 * 128 + loff);
        float4 v1 = *(const float4*)(g_G + (size_t)s1 * 128 + loff);
        float4 v2 = *(const float4*)(g_G + (size_t)s2 * 128 + loff);
        float4 v3 = *(const float4*)(g_G + (size_t)s3 * 128 + loff);
        acc.x += v0.x + v1.x + v2.x + v3.x;
        acc.y += v0.y + v1.y + v2.y + v3.y;
        acc.z += v0.z + v1.z + v2.z + v3.z;
        acc.w += v0.w + v1.w + v2.w + v3.w;
    }
    for (; j < end; j++) {
        int s = g_csr[j];
        float4 v = *(const float4*)(g_G + (size_t)s * 128 + loff);
        acc.x += v.x; acc.y += v.y; acc.z += v.z; acc.w += v.w;
    }

    float dv = g_dinv[node];
    float4 bb = *(const float4*)(b + lane * 4);
    float4 o;
    o.x = fmaxf(fmaf(dv, acc.x, bb.x), 0.0f);
    o.y = fmaxf(fmaf(dv, acc.y, bb.y), 0.0f);
    o.z = fmaxf(fmaf(dv, acc.z, bb.z), 0.0f);
    o.w = fmaxf(fmaf(dv, acc.w, bb.w), 0.0f);
    *(float4*)(g_X2 + (size_t)node * 128 + loff) = o;
}

// ------------------------------------------------------------------
// Output GEMM: out = X2 @ Wout + bout   (K=128, N=40)
// ------------------------------------------------------------------
__global__ __launch_bounds__(320) void out_gemm_kernel(
    const float* __restrict__ Wout, const float* __restrict__ bout,
    float* __restrict__ out, int n)
{
    __shared__ float Ws[128 * 40];
    __shared__ float Xs[32][132];
    __shared__ float bs[40];

    int tid = threadIdx.x;
    int row0 = blockIdx.x * 32;

    for (int idx = tid; idx < 128 * 40; idx += 320) Ws[idx] = Wout[idx];
    if (tid < 40) bs[tid] = bout[tid];
    for (int idx = tid; idx < 32 * 32; idx += 320) {
        int r = idx >> 5, k4 = idx & 31;
        int gr = row0 + r;
        float4 v = (gr < n) ? *(const float4*)(g_X2 + (size_t)gr * 128 + k4 * 4)
                            : make_float4(0.f, 0.f, 0.f, 0.f);
        *(float4*)(&Xs[r][k4 * 4]) = v;
    }
    __syncthreads();

    int col = tid % 40;
    int ty = tid / 40;
    float acc[4] = {0.f, 0.f, 0.f, 0.f};
#pragma unroll 4
    for (int k = 0; k < 128; k++) {
        float w = Ws[k * 40 + col];
#pragma unroll
        for (int r = 0; r < 4; r++)
            acc[r] = fmaf(Xs[ty + 8 * r][k], w, acc[r]);
    }
#pragma unroll
    for (int r = 0; r < 4; r++) {
        int row = row0 + ty + 8 * r;
        if (row < n) out[(size_t)row * 40 + col] = acc[r] + bs[col];
    }
}

// ------------------------------------------------------------------
// launch
// ------------------------------------------------------------------
extern "C" void kernel_launch(void* const* d_in, const int* in_sizes, int n_in,
                              void* d_out, int out_size)
{
    const float* x    = (const float*)d_in[0];
    const int*   ei   = (const int*)d_in[1];
    const float* W1   = (const float*)d_in[2];
    const float* b1   = (const float*)d_in[3];
    const float* W2   = (const float*)d_in[4];
    const float* b2   = (const float*)d_in[5];
    const float* Wout = (const float*)d_in[6];
    const float* bout = (const float*)d_in[7];
    float* out = (float*)d_out;

    int n = in_sizes[0] / 128;
    int e = in_sizes[1] / 2;
    const int* src = ei;
    const int* dst = ei + e;

    cudaFuncSetAttribute(gemm_mma_kernel,
                         cudaFuncAttributeMaxDynamicSharedMemorySize, GEMM_SMEM_B);

    int nb_n = (n + 255) / 256;
    int nb_e = (e + 255) / 256;
    int nb_scan = (n + 1023) / 1024;
    long long agg_threads = (long long)n * 32;
    int nb_agg = (int)((agg_threads + 255) / 256);
    int nb_out = (n + 31) / 32;

    // CSR build (shared across both layers)
    zero_cnt_kernel<<<nb_n, 256>>>(n);
    count_kernel<<<nb_e, 256>>>(dst, e);
    dinv_kernel<<<nb_n, 256>>>(n);
    scan_local_kernel<<<nb_scan, 256>>>(n);
    scan_bsums_kernel<<<1, 1024>>>(nb_scan);
    scan_add_kernel<<<nb_n, 256>>>(n, e);
    scatter_kernel<<<nb_e, 256>>>(src, dst, e);

    // layer 1
    gemm_mma_kernel<<<152, 256, GEMM_SMEM_B>>>(x, W1, n, 0);
    agg_fin_kernel<<<nb_agg, 256>>>(b1, n);

    // layer 2
    gemm_mma_kernel<<<152, 256, GEMM_SMEM_B>>>(nullptr, W2, n, 1);
    agg_fin_kernel<<<nb_agg, 256>>>(b2, n);

    // output projection
    out_gemm_kernel<<<nb_out, 320>>>(Wout, bout, out, n);
}